// round 13
// baseline (speedup 1.0000x reference)
#include <cuda_runtime.h>
#include <cuda_fp16.h>
#include <cfloat>

#define NN   50000
#define NE   800000
#define NEP  850000      // edges + self loops
#define HEADS 10
#define HID   10
#define CC    100        // HEADS*HID
#define NG    256
#define NOUT  10
#define NSLOPE 0.2f
#define GR   32          // gemm rows per block
#define TILE 32          // agg edges per smem tile

// ---------------- scratch (static device globals; zero-initialized) -----------
__device__ __half g_Ah[NN * CC];       // h in fp16 (aggregation gather)
__device__ float  g_B[NN * CC];        // layer input / aggregation output
__device__ int    g_SRC[NEP];
__device__ int    g_DST[NEP];
__device__ int    g_CSRC[NEP];         // CSR: src per position (sorted by dst)
__device__ int    g_CNT[NN];           // degree counts; re-zeroed by k_scatter each call
__device__ int    g_ROW[NN + 1];
__device__ int    g_WOFF[NN];
__device__ int    g_BATCH[NN];
__device__ float2 g_S2src[NN * HEADS]; // (s, exp(0.2*s))
__device__ float2 g_S2dst[NN * HEADS];
__device__ float  g_gsum[NG * CC];     // zeroed by k_convert each call
__device__ float  g_cnt[NG];

// ---- launch 1: convert edges+batch, degree count, zero gsum (is64 inline) ----
__global__ void k_convert(const void* ei, const void* bp) {
    __shared__ int s_is64;
    if (threadIdx.x == 0) {
        const long long* p = (const long long*)ei;
        int ok = 1;
#pragma unroll
        for (int q = 0; q < 16; q++) {
            long long v = p[q];
            if (v < 0 || v >= NN) ok = 0;
        }
        s_is64 = ok;
    }
    __syncthreads();
    int is64 = s_is64;
    int e = blockIdx.x * blockDim.x + threadIdx.x;
    if (e < NEP) {
        int s, d;
        if (e < NE) {
            if (is64) {
                const long long* p = (const long long*)ei;
                s = (int)p[e]; d = (int)p[NE + e];
            } else {
                const int* p = (const int*)ei;
                s = p[e]; d = p[NE + e];
            }
        } else {
            s = d = e - NE;   // self loop
        }
        g_SRC[e] = s;
        g_DST[e] = d;
        atomicAdd(&g_CNT[d], 1);
    }
    if (e < NN) {
        g_BATCH[e] = is64 ? (int)((const long long*)bp)[e] : ((const int*)bp)[e];
    }
    if (e < NG * CC) g_gsum[e] = 0.f;   // used at launches 10-11 this call
}
// ---- launch 2: CSR scan + per-graph counts -----------------------------------
__global__ __launch_bounds__(1024) void k_scan() {
    __shared__ int wsum[32];
    __shared__ int s_carry;
    int tid = threadIdx.x;
    int lane = tid & 31, warp = tid >> 5;
    if (tid == 0) s_carry = 0;
    __syncthreads();
    for (int base = 0; base < NN; base += 1024) {
        int v = (base + tid < NN) ? g_CNT[base + tid] : 0;
        int x = v;
#pragma unroll
        for (int o = 1; o < 32; o <<= 1) {
            int y = __shfl_up_sync(~0u, x, o);
            if (lane >= o) x += y;
        }
        if (lane == 31) wsum[warp] = x;
        __syncthreads();
        if (warp == 0) {
            int w = wsum[lane];
#pragma unroll
            for (int o = 1; o < 32; o <<= 1) {
                int y = __shfl_up_sync(~0u, w, o);
                if (lane >= o) w += y;
            }
            wsum[lane] = w;
        }
        __syncthreads();
        int warpoff = (warp == 0) ? 0 : wsum[warp - 1];
        int ex = s_carry + warpoff + x - v;
        if (base + tid < NN) { g_ROW[base + tid] = ex; g_WOFF[base + tid] = ex; }
        __syncthreads();
        if (tid == 1023) s_carry += warpoff + x;
        __syncthreads();
    }
    if (tid == 0) g_ROW[NN] = s_carry;
    // per-graph node counts (batch sorted)
    if (tid < NG) {
        int g = tid;
        int lo = 0, hi = NN;
        while (lo < hi) { int mid = (lo + hi) >> 1; if (g_BATCH[mid] < g) lo = mid + 1; else hi = mid; }
        int a = lo;
        lo = 0; hi = NN;
        while (lo < hi) { int mid = (lo + hi) >> 1; if (g_BATCH[mid] < g + 1) lo = mid + 1; else hi = mid; }
        g_cnt[g] = (float)(lo - a);
    }
}
// ---- launch 3: scatter + re-zero CNT for next call ---------------------------
__global__ void k_scatter() {
    int e = blockIdx.x * blockDim.x + threadIdx.x;
    if (e < NEP) {
        int d = g_DST[e];
        int pos = atomicAdd(&g_WOFF[d], 1);
        g_CSRC[pos] = g_SRC[e];
    }
    if (e < NN) g_CNT[e] = 0;           // ready for next kernel_launch call
}

// ---- launch 4 (CAPTURED): h = X@W (fp16 out) + score-exp tables --------------
__global__ __launch_bounds__(128) void k_gemm(const float* __restrict__ Xext,
                                              const float* __restrict__ W,
                                              const float* __restrict__ asrc,
                                              const float* __restrict__ adst,
                                              int Din, int use_gb) {
    __shared__ float Wt[64 * 128];       // 32KB; reused as output stage (needs 3200)
    __shared__ float Xs[64][GR + 4];
    const float* X = use_gb ? (const float*)g_B : Xext;
    int n0 = blockIdx.x * GR;
    int ct = threadIdx.x & 31;
    int rt = threadIdx.x >> 5;
    float acc[8][4];
#pragma unroll
    for (int i = 0; i < 8; i++)
#pragma unroll
        for (int j = 0; j < 4; j++) acc[i][j] = 0.f;

    for (int k0 = 0; k0 < Din; k0 += 64) {
        int kk = min(64, Din - k0);
        for (int idx = threadIdx.x; idx < kk * 128; idx += 128) {
            int k = idx >> 7, c = idx & 127;
            Wt[idx] = (c < CC) ? W[(size_t)(k0 + k) * CC + c] : 0.f;
        }
        for (int idx = threadIdx.x; idx < GR * kk; idx += 128) {
            int r = idx / kk, k = idx - r * kk;
            int n = n0 + r;
            Xs[k][r] = (n < NN) ? X[(size_t)n * Din + k0 + k] : 0.f;
        }
        __syncthreads();
        for (int k = 0; k < kk; k++) {
            float4 w  = *(const float4*)&Wt[k * 128 + ct * 4];
            float4 xa = *(const float4*)&Xs[k][rt * 8];
            float4 xb = *(const float4*)&Xs[k][rt * 8 + 4];
            float xr[8] = {xa.x, xa.y, xa.z, xa.w, xb.x, xb.y, xb.z, xb.w};
            float wr[4] = {w.x, w.y, w.z, w.w};
#pragma unroll
            for (int i = 0; i < 8; i++)
#pragma unroll
                for (int j = 0; j < 4; j++) acc[i][j] += xr[i] * wr[j];
        }
        __syncthreads();
    }
    // epilogue: fp16 store + smem stage
    float* stage = Wt;   // [GR][CC]
    if (ct < 25) {
#pragma unroll
        for (int i = 0; i < 8; i++) {
            int r = rt * 8 + i;
            int n = n0 + r;
            stage[r * CC + ct * 4 + 0] = acc[i][0];
            stage[r * CC + ct * 4 + 1] = acc[i][1];
            stage[r * CC + ct * 4 + 2] = acc[i][2];
            stage[r * CC + ct * 4 + 3] = acc[i][3];
            if (n < NN) {
                __half2* hp = (__half2*)&g_Ah[(size_t)n * CC + ct * 4];
                hp[0] = __floats2half2_rn(acc[i][0], acc[i][1]);
                hp[1] = __floats2half2_rn(acc[i][2], acc[i][3]);
            }
        }
    }
    __syncthreads();
    // scores + (s, e^{0.2s}) tables: 32 rows x 10 heads
    for (int idx = threadIdx.x; idx < GR * HEADS; idx += 128) {
        int r = idx / HEADS, h = idx - r * HEADS;
        int n = n0 + r;
        if (n < NN) {
            float s1 = 0.f, s2 = 0.f;
#pragma unroll
            for (int f = 0; f < HID; f++) {
                float v = stage[r * CC + h * HID + f];
                s1 += v * asrc[h * HID + f];
                s2 += v * adst[h * HID + f];
            }
            g_S2src[n * HEADS + h] = make_float2(s1, __expf(NSLOPE * s1));
            g_S2dst[n * HEADS + h] = make_float2(s2, __expf(NSLOPE * s2));
        }
    }
}

// ---- fused softmax + aggregation (block per dst), MUFU-free edge loop --------
// t = e^{0.2 s_s} * e^{0.2 s_d};  exp(leaky(ss+sd)) = (ss+sd>=0) ? t^5 : t
__global__ __launch_bounds__(128) void k_agg(const float* __restrict__ bias) {
    int d = blockIdx.x;
    int t = threadIdx.x;
    __shared__ float exv[TILE * HEADS];
    __shared__ int   ssrc[TILE];
    __shared__ float2 sdst[HEADS];
    __shared__ float red[3 * 50];       // partials from the odd-edge group
    int row0 = g_ROW[d], row1 = g_ROW[d + 1];
    if (t < HEADS) sdst[t] = g_S2dst[d * HEADS + t];
    __syncthreads();
    bool lo = (t < 50);
    bool hi = (t >= 64 && t < 114);
    int cp = lo ? t : (t - 64);          // col pair id 0..49
    int hh = cp / 5;                     // head of cols 2cp, 2cp+1
    float ax = 0.f, ay = 0.f, dn = 0.f;
    for (int t0 = row0; t0 < row1; t0 += TILE) {
        int nt = min(TILE, row1 - t0);
        // phase A: factorized exp(alpha), no MUFU
        for (int idx = t; idx < nt * HEADS; idx += 128) {
            int j = idx / HEADS, h = idx - j * HEADS;
            int s = g_CSRC[t0 + j];
            if (h == 0) ssrc[j] = s;
            float2 S = g_S2src[s * HEADS + h];
            float2 D = sdst[h];
            float a  = S.x + D.x;
            float tt = S.y * D.y;        // e^{0.2(ss+sd)}
            float t2 = tt * tt;
            exv[j * HEADS + h] = (a >= 0.f) ? (t2 * t2 * tt) : tt;
        }
        __syncthreads();
        // phase B: weighted gather, 2-way edge-parallel
        if (lo || hi) {
            for (int j = lo ? 0 : 1; j < nt; j += 2) {
                int s = ssrc[j];
                float ex = exv[j * HEADS + hh];
                __half2 hv = *(const __half2*)&g_Ah[(size_t)s * CC + 2 * cp];
                float2 f = __half22float2(hv);
                ax += ex * f.x;
                ay += ex * f.y;
                dn += ex;
            }
        }
        __syncthreads();
    }
    if (hi) { red[cp] = ax; red[50 + cp] = ay; red[100 + cp] = dn; }
    __syncthreads();
    if (lo) {
        ax += red[cp];
        ay += red[50 + cp];
        dn += red[100 + cp];
        float invd = 1.f / dn;
        float vx = ax * invd + bias[2 * cp];
        float vy = ay * invd + bias[2 * cp + 1];
        vx = vx > 0.f ? vx : 0.f;
        vy = vy > 0.f ? vy : 0.f;
        *(float2*)&g_B[(size_t)d * CC + 2 * cp] = make_float2(vx, vy);
    }
}

// ---------------- pooling -----------------------------------------------------
__global__ __launch_bounds__(128) void k_pool() {
    int c = threadIdx.x;
    if (c >= CC) return;
    int n0 = blockIdx.x * 256;
    if (n0 >= NN) return;
    int nend = min(n0 + 256, NN);
    int cur = g_BATCH[n0];
    float acc = 0.f;
    for (int n = n0; n < nend; n++) {
        int g = g_BATCH[n];
        if (g != cur) { atomicAdd(&g_gsum[cur * CC + c], acc); acc = 0.f; cur = g; }
        acc += g_B[(size_t)n * CC + c];
    }
    atomicAdd(&g_gsum[cur * CC + c], acc);
}

// ---------------- final FC ----------------------------------------------------
__global__ void k_fc(const float* __restrict__ Wfc, const float* __restrict__ bfc,
                     float* __restrict__ out) {
    int idx = blockIdx.x * blockDim.x + threadIdx.x;
    if (idx >= NG * NOUT) return;
    int g = idx / NOUT, o = idx - g * NOUT;
    float inv = 1.f / fmaxf(g_cnt[g], 1.f);
    float s = 0.f;
#pragma unroll 4
    for (int c = 0; c < CC; c++) s += g_gsum[g * CC + c] * Wfc[c * NOUT + o];
    out[idx] = s * inv + bfc[o];
}

// ---------------- driver ------------------------------------------------------
extern "C" void kernel_launch(void* const* d_in, const int* in_sizes, int n_in,
                              void* d_out, int out_size) {
    const float* x     = (const float*)d_in[0];
    const void*  ei    = d_in[1];
    const void*  batch = d_in[2];
    const float* W[3]    = { (const float*)d_in[3],  (const float*)d_in[7],  (const float*)d_in[11] };
    const float* asrc[3] = { (const float*)d_in[4],  (const float*)d_in[8],  (const float*)d_in[12] };
    const float* adst[3] = { (const float*)d_in[5],  (const float*)d_in[9],  (const float*)d_in[13] };
    const float* bb[3]   = { (const float*)d_in[6],  (const float*)d_in[10], (const float*)d_in[14] };
    const float* Wfc = (const float*)d_in[15];
    const float* bfc = (const float*)d_in[16];
    float* out = (float*)d_out;

    const int TB = 256;
    int gE = (NEP + TB - 1) / TB;
    int gG = (NN + GR - 1) / GR;

    // prep: 3 launches; g_CNT pre-zeroed (static init / previous call's scatter)
    k_convert<<<gE, TB>>>(ei, batch);
    k_scan<<<1, 1024>>>();
    k_scatter<<<gE, TB>>>();

    // launch 4 = gemm L0 (ncu capture slot)
    for (int l = 0; l < 3; l++) {
        int Din = (l == 0) ? 128 : CC;
        k_gemm<<<gG, 128>>>(x, W[l], asrc[l], adst[l], Din, l > 0 ? 1 : 0);
        k_agg<<<NN, 128>>>(bb[l]);
    }

    k_pool<<<(NN + 255) / 256, 128>>>();
    k_fc<<<(NG * NOUT + TB - 1) / TB, TB>>>(Wfc, bfc, out);
}

// round 14
// speedup vs baseline: 1.1330x; 1.1330x over previous
#include <cuda_runtime.h>
#include <cuda_fp16.h>
#include <cfloat>

#define NN   50000
#define NE   800000
#define NEP  850000      // edges + self loops
#define HEADS 10
#define HID   10
#define CC    100        // HEADS*HID
#define NG    256
#define NOUT  10
#define NSLOPE 0.2f
#define GR   64          // gemm rows per block
#define KCH  32          // gemm k-chunk
#define TILE 32          // agg edges per smem tile

// ---------------- scratch (static device globals; zero-initialized) -----------
__device__ __half g_Ah[NN * CC];       // h in fp16 (aggregation gather)
__device__ float  g_B[NN * CC];        // layer input / aggregation output
__device__ int    g_SRC[NEP];
__device__ int    g_DST[NEP];
__device__ int    g_CSRC[NEP];         // CSR: src per position (sorted by dst)
__device__ int    g_CNT[NN];           // degree counts; re-zeroed by k_scatter each call
__device__ int    g_ROW[NN + 1];
__device__ int    g_WOFF[NN];
__device__ int    g_BATCH[NN];
__device__ float2 g_S2src[NN * HEADS]; // (s, exp(0.2*s))
__device__ float2 g_S2dst[NN * HEADS];
__device__ float  g_gsum[NG * CC];     // zeroed by k_convert each call
__device__ float  g_cnt[NG];

// ---- launch 1: convert edges+batch, degree count, zero gsum (is64 inline) ----
__global__ void k_convert(const void* ei, const void* bp) {
    __shared__ int s_is64;
    if (threadIdx.x == 0) {
        const long long* p = (const long long*)ei;
        int ok = 1;
#pragma unroll
        for (int q = 0; q < 16; q++) {
            long long v = p[q];
            if (v < 0 || v >= NN) ok = 0;
        }
        s_is64 = ok;
    }
    __syncthreads();
    int is64 = s_is64;
    int e = blockIdx.x * blockDim.x + threadIdx.x;
    if (e < NEP) {
        int s, d;
        if (e < NE) {
            if (is64) {
                const long long* p = (const long long*)ei;
                s = (int)p[e]; d = (int)p[NE + e];
            } else {
                const int* p = (const int*)ei;
                s = p[e]; d = p[NE + e];
            }
        } else {
            s = d = e - NE;   // self loop
        }
        g_SRC[e] = s;
        g_DST[e] = d;
        atomicAdd(&g_CNT[d], 1);
    }
    if (e < NN) {
        g_BATCH[e] = is64 ? (int)((const long long*)bp)[e] : ((const int*)bp)[e];
    }
    if (e < NG * CC) g_gsum[e] = 0.f;   // used at pooling this call
}
// ---- launch 2: CSR scan + per-graph counts -----------------------------------
__global__ __launch_bounds__(1024) void k_scan() {
    __shared__ int wsum[32];
    __shared__ int s_carry;
    int tid = threadIdx.x;
    int lane = tid & 31, warp = tid >> 5;
    if (tid == 0) s_carry = 0;
    __syncthreads();
    for (int base = 0; base < NN; base += 1024) {
        int v = (base + tid < NN) ? g_CNT[base + tid] : 0;
        int x = v;
#pragma unroll
        for (int o = 1; o < 32; o <<= 1) {
            int y = __shfl_up_sync(~0u, x, o);
            if (lane >= o) x += y;
        }
        if (lane == 31) wsum[warp] = x;
        __syncthreads();
        if (warp == 0) {
            int w = wsum[lane];
#pragma unroll
            for (int o = 1; o < 32; o <<= 1) {
                int y = __shfl_up_sync(~0u, w, o);
                if (lane >= o) w += y;
            }
            wsum[lane] = w;
        }
        __syncthreads();
        int warpoff = (warp == 0) ? 0 : wsum[warp - 1];
        int ex = s_carry + warpoff + x - v;
        if (base + tid < NN) { g_ROW[base + tid] = ex; g_WOFF[base + tid] = ex; }
        __syncthreads();
        if (tid == 1023) s_carry += warpoff + x;
        __syncthreads();
    }
    if (tid == 0) g_ROW[NN] = s_carry;
    if (tid < NG) {
        int g = tid;
        int lo = 0, hi = NN;
        while (lo < hi) { int mid = (lo + hi) >> 1; if (g_BATCH[mid] < g) lo = mid + 1; else hi = mid; }
        int a = lo;
        lo = 0; hi = NN;
        while (lo < hi) { int mid = (lo + hi) >> 1; if (g_BATCH[mid] < g + 1) lo = mid + 1; else hi = mid; }
        g_cnt[g] = (float)(lo - a);
    }
}
// ---- launch 3: scatter + re-zero CNT for next call ---------------------------
__global__ void k_scatter() {
    int e = blockIdx.x * blockDim.x + threadIdx.x;
    if (e < NEP) {
        int d = g_DST[e];
        int pos = atomicAdd(&g_WOFF[d], 1);
        g_CSRC[pos] = g_SRC[e];
    }
    if (e < NN) g_CNT[e] = 0;
}

// ---- launch 4 (CAPTURED): h = X@W (fp16 out) + score-exp tables --------------
// 256 threads, 64 rows/block, 8x4 register tile, k-chunk 32. smem 24.7KB.
__global__ __launch_bounds__(256) void k_gemm(const float* __restrict__ Xext,
                                              const float* __restrict__ W,
                                              const float* __restrict__ asrc,
                                              const float* __restrict__ adst,
                                              int Din, int use_gb) {
    __shared__ float Wt[KCH * 128];      // 16KB; reused as 32x100 score stage (12.8KB)
    __shared__ float Xs[KCH][GR + 4];    // 8.7KB (68-float row stride, 16B aligned)
    const float* X = use_gb ? (const float*)g_B : Xext;
    int n0 = blockIdx.x * GR;
    int ct = threadIdx.x & 31;
    int rt = threadIdx.x >> 5;           // 0..7 -> rows rt*8..rt*8+7
    float acc[8][4];
#pragma unroll
    for (int i = 0; i < 8; i++)
#pragma unroll
        for (int j = 0; j < 4; j++) acc[i][j] = 0.f;

    for (int k0 = 0; k0 < Din; k0 += KCH) {
        int kk = min(KCH, Din - k0);
        for (int idx = threadIdx.x; idx < kk * 128; idx += 256) {
            int k = idx >> 7, c = idx & 127;
            Wt[idx] = (c < CC) ? W[(size_t)(k0 + k) * CC + c] : 0.f;
        }
        for (int idx = threadIdx.x; idx < GR * kk; idx += 256) {
            int r = idx / kk, k = idx - r * kk;
            int n = n0 + r;
            Xs[k][r] = (n < NN) ? X[(size_t)n * Din + k0 + k] : 0.f;
        }
        __syncthreads();
#pragma unroll 8
        for (int k = 0; k < kk; k++) {
            float4 w  = *(const float4*)&Wt[k * 128 + ct * 4];
            float4 xa = *(const float4*)&Xs[k][rt * 8];
            float4 xb = *(const float4*)&Xs[k][rt * 8 + 4];
            float xr[8] = {xa.x, xa.y, xa.z, xa.w, xb.x, xb.y, xb.z, xb.w};
            float wr[4] = {w.x, w.y, w.z, w.w};
#pragma unroll
            for (int i = 0; i < 8; i++)
#pragma unroll
                for (int j = 0; j < 4; j++) acc[i][j] += xr[i] * wr[j];
        }
        __syncthreads();
    }
    // fp16 feature store straight from registers
    if (ct < 25) {
#pragma unroll
        for (int i = 0; i < 8; i++) {
            int n = n0 + rt * 8 + i;
            if (n < NN) {
                __half2* hp = (__half2*)&g_Ah[(size_t)n * CC + ct * 4];
                hp[0] = __floats2half2_rn(acc[i][0], acc[i][1]);
                hp[1] = __floats2half2_rn(acc[i][2], acc[i][3]);
            }
        }
    }
    // scores in two 32-row passes staged through Wt (32*100 floats = 12.8KB)
    float* stage = Wt;
#pragma unroll
    for (int half = 0; half < 2; half++) {
        __syncthreads();
        if (ct < 25 && (rt >> 2) == half) {
            int rl = (rt & 3) * 8;       // local row 0,8,16,24
#pragma unroll
            for (int i = 0; i < 8; i++) {
                stage[(rl + i) * CC + ct * 4 + 0] = acc[i][0];
                stage[(rl + i) * CC + ct * 4 + 1] = acc[i][1];
                stage[(rl + i) * CC + ct * 4 + 2] = acc[i][2];
                stage[(rl + i) * CC + ct * 4 + 3] = acc[i][3];
            }
        }
        __syncthreads();
        for (int idx = threadIdx.x; idx < 32 * HEADS; idx += 256) {
            int r = idx / HEADS, h = idx - r * HEADS;
            int n = n0 + half * 32 + r;
            if (n < NN) {
                float s1 = 0.f, s2 = 0.f;
#pragma unroll
                for (int f = 0; f < HID; f++) {
                    float v = stage[r * CC + h * HID + f];
                    s1 += v * asrc[h * HID + f];
                    s2 += v * adst[h * HID + f];
                }
                g_S2src[n * HEADS + h] = make_float2(s1, __expf(NSLOPE * s1));
                g_S2dst[n * HEADS + h] = make_float2(s2, __expf(NSLOPE * s2));
            }
        }
    }
}

// ---- fused softmax + aggregation (block per dst), MUFU-free edge loop --------
__global__ __launch_bounds__(128) void k_agg(const float* __restrict__ bias) {
    int d = blockIdx.x;
    int t = threadIdx.x;
    __shared__ float exv[TILE * HEADS];
    __shared__ int   ssrc[TILE];
    __shared__ float2 sdst[HEADS];
    __shared__ float red[3 * 50];
    int row0 = g_ROW[d], row1 = g_ROW[d + 1];
    if (t < HEADS) sdst[t] = g_S2dst[d * HEADS + t];
    __syncthreads();
    bool lo = (t < 50);
    bool hi = (t >= 64 && t < 114);
    int cp = lo ? t : (t - 64);
    int hh = cp / 5;
    float ax = 0.f, ay = 0.f, dn = 0.f;
    for (int t0 = row0; t0 < row1; t0 += TILE) {
        int nt = min(TILE, row1 - t0);
        for (int idx = t; idx < nt * HEADS; idx += 128) {
            int j = idx / HEADS, h = idx - j * HEADS;
            int s = g_CSRC[t0 + j];
            if (h == 0) ssrc[j] = s;
            float2 S = g_S2src[s * HEADS + h];
            float2 D = sdst[h];
            float a  = S.x + D.x;
            float tt = S.y * D.y;        // e^{0.2(ss+sd)}
            float t2 = tt * tt;
            exv[j * HEADS + h] = (a >= 0.f) ? (t2 * t2 * tt) : tt;
        }
        __syncthreads();
        if (lo || hi) {
            for (int j = lo ? 0 : 1; j < nt; j += 2) {
                int s = ssrc[j];
                float ex = exv[j * HEADS + hh];
                __half2 hv = *(const __half2*)&g_Ah[(size_t)s * CC + 2 * cp];
                float2 f = __half22float2(hv);
                ax += ex * f.x;
                ay += ex * f.y;
                dn += ex;
            }
        }
        __syncthreads();
    }
    if (hi) { red[cp] = ax; red[50 + cp] = ay; red[100 + cp] = dn; }
    __syncthreads();
    if (lo) {
        ax += red[cp];
        ay += red[50 + cp];
        dn += red[100 + cp];
        float invd = 1.f / dn;
        float vx = ax * invd + bias[2 * cp];
        float vy = ay * invd + bias[2 * cp + 1];
        vx = vx > 0.f ? vx : 0.f;
        vy = vy > 0.f ? vy : 0.f;
        *(float2*)&g_B[(size_t)d * CC + 2 * cp] = make_float2(vx, vy);
    }
}

// ---------------- pooling -----------------------------------------------------
__global__ __launch_bounds__(128) void k_pool() {
    int c = threadIdx.x;
    if (c >= CC) return;
    int n0 = blockIdx.x * 256;
    if (n0 >= NN) return;
    int nend = min(n0 + 256, NN);
    int cur = g_BATCH[n0];
    float acc = 0.f;
    for (int n = n0; n < nend; n++) {
        int g = g_BATCH[n];
        if (g != cur) { atomicAdd(&g_gsum[cur * CC + c], acc); acc = 0.f; cur = g; }
        acc += g_B[(size_t)n * CC + c];
    }
    atomicAdd(&g_gsum[cur * CC + c], acc);
}

// ---------------- final FC ----------------------------------------------------
__global__ void k_fc(const float* __restrict__ Wfc, const float* __restrict__ bfc,
                     float* __restrict__ out) {
    int idx = blockIdx.x * blockDim.x + threadIdx.x;
    if (idx >= NG * NOUT) return;
    int g = idx / NOUT, o = idx - g * NOUT;
    float inv = 1.f / fmaxf(g_cnt[g], 1.f);
    float s = 0.f;
#pragma unroll 4
    for (int c = 0; c < CC; c++) s += g_gsum[g * CC + c] * Wfc[c * NOUT + o];
    out[idx] = s * inv + bfc[o];
}

// ---------------- driver ------------------------------------------------------
extern "C" void kernel_launch(void* const* d_in, const int* in_sizes, int n_in,
                              void* d_out, int out_size) {
    const float* x     = (const float*)d_in[0];
    const void*  ei    = d_in[1];
    const void*  batch = d_in[2];
    const float* W[3]    = { (const float*)d_in[3],  (const float*)d_in[7],  (const float*)d_in[11] };
    const float* asrc[3] = { (const float*)d_in[4],  (const float*)d_in[8],  (const float*)d_in[12] };
    const float* adst[3] = { (const float*)d_in[5],  (const float*)d_in[9],  (const float*)d_in[13] };
    const float* bb[3]   = { (const float*)d_in[6],  (const float*)d_in[10], (const float*)d_in[14] };
    const float* Wfc = (const float*)d_in[15];
    const float* bfc = (const float*)d_in[16];
    float* out = (float*)d_out;

    const int TB = 256;
    int gE = (NEP + TB - 1) / TB;
    int gG = (NN + GR - 1) / GR;

    // prep: 3 launches; g_CNT pre-zeroed (static init / previous call's scatter)
    k_convert<<<gE, TB>>>(ei, batch);
    k_scan<<<1, 1024>>>();
    k_scatter<<<gE, TB>>>();

    // launch 4 = gemm L0 (ncu capture slot)
    for (int l = 0; l < 3; l++) {
        int Din = (l == 0) ? 128 : CC;
        k_gemm<<<gG, 256>>>(x, W[l], asrc[l], adst[l], Din, l > 0 ? 1 : 0);
        k_agg<<<NN, 128>>>(bb[l]);
    }

    k_pool<<<(NN + 255) / 256, 128>>>();
    k_fc<<<(NG * NOUT + TB - 1) / TB, TB>>>(Wfc, bfc, out);
}